// round 1
// baseline (speedup 1.0000x reference)
#include <cuda_runtime.h>

// AOLayer: out[b,n,a] = ang(b,n,a) * rad(b,n,a)
//   d   = pos[b,n,:] - centers[a,:]
//   r2  = dot(d,d)
//   rad = sum_p coeffs[a,p] * exp(-exps[a,p] * r2)
//   ang = prod_dim d^powers[a,dim]   (powers in {0,1,2})
//
// B=512, N=32, A=256, P=6. Output (B*N, A) row-major, 4.19M floats.
// Compute-bound: 6 EX2 + ~24 FMA-pipe ops per element.

#define A_DIM 256
#define P_DIM 6
#define BN_DIM (512 * 32)
#define ROWS_PER_BLOCK 16

__device__ __forceinline__ float ex2_approx(float x) {
    float r;
    asm("ex2.approx.f32 %0, %1;" : "=f"(r) : "f"(x));
    return r;
}

__global__ void __launch_bounds__(A_DIM) aolayer_kernel(
    const float* __restrict__ pos,      // [BN, 3]
    const float* __restrict__ centers,  // [A, 3]
    const float* __restrict__ exps,     // [A, P]
    const float* __restrict__ coeffs,   // [A, P]
    const int*   __restrict__ powers,   // [A, 3]
    float* __restrict__ out)            // [BN, A]
{
    const int a = threadIdx.x;

    // ---- per-atom constants, loaded once per block ----
    const float cx = centers[a * 3 + 0];
    const float cy = centers[a * 3 + 1];
    const float cz = centers[a * 3 + 2];

    // pre-fold -log2(e) into the exponent so inner loop is FMUL + EX2
    const float NEG_LOG2E = -1.4426950408889634f;
    float ep[P_DIM], co[P_DIM];
#pragma unroll
    for (int p = 0; p < P_DIM; p++) {
        ep[p] = exps[a * P_DIM + p] * NEG_LOG2E;
        co[p] = coeffs[a * P_DIM + p];
    }

    const int px = powers[a * 3 + 0];
    const int py = powers[a * 3 + 1];
    const int pz = powers[a * 3 + 2];
    // loop-invariant predicates: linear term present (p>=1), quadratic (p==2)
    const bool lx = (px >= 1), qx = (px == 2);
    const bool ly = (py >= 1), qy = (py == 2);
    const bool lz = (pz >= 1), qz = (pz == 2);

    // ---- stage pos rows for this block into shared memory ----
    __shared__ float spos[ROWS_PER_BLOCK * 3];
    const int row0 = blockIdx.x * ROWS_PER_BLOCK;
    if (threadIdx.x < ROWS_PER_BLOCK * 3) {
        spos[threadIdx.x] = pos[row0 * 3 + threadIdx.x];
    }
    __syncthreads();

    float* out_base = out + (size_t)row0 * A_DIM + a;

#pragma unroll
    for (int r = 0; r < ROWS_PER_BLOCK; r++) {
        const float dx = spos[r * 3 + 0] - cx;
        const float dy = spos[r * 3 + 1] - cy;
        const float dz = spos[r * 3 + 2] - cz;

        const float r2 = fmaf(dx, dx, fmaf(dy, dy, dz * dz));

        // radial: sum_p co[p] * 2^(ep[p] * r2)
        float rad = 0.0f;
#pragma unroll
        for (int p = 0; p < P_DIM; p++) {
            rad = fmaf(co[p], ex2_approx(ep[p] * r2), rad);
        }

        // angular: d^p with p in {0,1,2}, branchless
        float tx = lx ? dx : 1.0f;  tx = qx ? tx * dx : tx;
        float ty = ly ? dy : 1.0f;  ty = qy ? ty * dy : ty;
        float tz = lz ? dz : 1.0f;  tz = qz ? tz * dz : tz;

        out_base[(size_t)r * A_DIM] = tx * ty * tz * rad;
    }
}

extern "C" void kernel_launch(void* const* d_in, const int* in_sizes, int n_in,
                              void* d_out, int out_size) {
    const float* pos     = (const float*)d_in[0];
    const float* centers = (const float*)d_in[1];
    const float* exps    = (const float*)d_in[2];
    const float* coeffs  = (const float*)d_in[3];
    const int*   powers  = (const int*)d_in[4];
    float* out = (float*)d_out;

    dim3 grid(BN_DIM / ROWS_PER_BLOCK);  // 1024 blocks
    dim3 block(A_DIM);                   // 256 threads, one per atom
    aolayer_kernel<<<grid, block>>>(pos, centers, exps, coeffs, powers, out);
}